// round 15
// baseline (speedup 1.0000x reference)
#include <cuda_runtime.h>
#include <math.h>
#include <stdint.h>

// ---------------- problem constants ----------------
#define BB   2
#define SS   1024
#define PP   1024
#define TT   2048           // P + S
#define HH   4096
#define NQH  32
#define NKVH 8
#define DD   128
#define GQ   4              // NQH / NKVH
#define MM   (BB*SS)        // 2048 token rows
#define QKVN ((NQH + 2*NKVH)*DD)   // 6144
#define KK   4096           // GEMM K dim for both projections
#define ATTN_SCALE 0.08838834764831845f   // 1/sqrt(128)

// ---------------- device scratch (no allocation allowed) ----------------
__device__ float g_qkv [(size_t)MM * QKVN];           // 50.3 MB
__device__ float g_kall[(size_t)BB * TT * NKVH * DD]; // 16.8 MB
__device__ float g_vall[(size_t)BB * TT * NKVH * DD]; // 16.8 MB
__device__ float g_attn[(size_t)MM * NQH * DD];       // 33.5 MB

// =====================================================================
// tf32 helpers (mma.sync — baseline sm_80 feature, OK on plain sm_103)
// =====================================================================
__device__ __forceinline__ float to_tf32(float x) {
    uint32_t h;
    asm("cvt.rna.tf32.f32 %0, %1;" : "=r"(h) : "f"(x));
    return __uint_as_float(h);
}

__device__ __forceinline__ void mma1688(float* c,
                                        float a0, float a1, float a2, float a3,
                                        float b0, float b1) {
    asm volatile(
        "mma.sync.aligned.m16n8k8.row.col.f32.tf32.tf32.f32 "
        "{%0,%1,%2,%3}, {%4,%5,%6,%7}, {%8,%9}, {%0,%1,%2,%3};"
        : "+f"(c[0]), "+f"(c[1]), "+f"(c[2]), "+f"(c[3])
        : "r"(__float_as_uint(a0)), "r"(__float_as_uint(a1)),
          "r"(__float_as_uint(a2)), "r"(__float_as_uint(a3)),
          "r"(__float_as_uint(b0)), "r"(__float_as_uint(b1)));
}

// =====================================================================
// tf32 tensor-core GEMM: C[M,N] = A[M,K=4096] @ B[K,N]  (both row-major)
// CTA 128x128, BK=32, 8 warps (4x2) of 32x64, double-buffered SMEM.
//
// SMEM permuted layout: element k of a row goes to column (k%4)*8 + k/4,
// row stride 36 floats. A thread's m16n8k8 fragment elements for all 4
// k-steps of a stage are then contiguous -> 2x LDS.128 per row/col,
// bank-conflict-free at stride 36. A stored by M-row, B stored by N-col
// (transpose folded into the STS fill), so B reads original [K][N].
//
// SMEM: 2 stages x (As 128*36 + Bs 128*36) floats = 73,728 B.
// =====================================================================
#define GEMM_SMEM (2 * (128*36 + 128*36) * 4)   // 73728
#define STG_F     (128*36 + 128*36)             // floats per stage

__device__ __forceinline__ void tc_gemm(const float* __restrict__ A,
                                        const float* __restrict__ B,
                                        float* __restrict__ C, int N)
{
    extern __shared__ float sm[];
    const int tid  = threadIdx.x;
    const int wid  = tid >> 5, lane = tid & 31;
    const int wm   = wid & 3,  wn   = wid >> 2;   // warp at (wm*32, wn*64)
    const int g    = lane >> 2, t   = lane & 3;
    const int bm   = blockIdx.y, bn = blockIdx.x;

    const float* Ag = A + (size_t)(bm * 128) * KK;
    const float* Bg = B + bn * 128;

    // fill index decomposition (4 float4 per thread per tile)
    const int ar = (tid << 2) >> 3;            // placeholder (recomputed below)
    (void)ar;

    float4 aS[4], bS[4];

    // ---- prologue: load kt=0 ----
    #pragma unroll
    for (int q = 0; q < 4; q++) {
        int idx = tid + q * 256;
        int r = idx >> 3, kb = idx & 7;            // A: row r, float4 kb
        int k = idx >> 5, nb = idx & 31;           // B: k-row, float4 nb
        aS[q] = *(const float4*)(Ag + (size_t)r * KK + kb * 4);
        bS[q] = *(const float4*)(Bg + (size_t)k * N + nb * 4);
    }
    {
        float* As = sm;
        float* Bs = sm + 128 * 36;
        #pragma unroll
        for (int q = 0; q < 4; q++) {
            int idx = tid + q * 256;
            int r = idx >> 3, kb = idx & 7;
            As[r * 36 + 0  + kb] = to_tf32(aS[q].x);
            As[r * 36 + 8  + kb] = to_tf32(aS[q].y);
            As[r * 36 + 16 + kb] = to_tf32(aS[q].z);
            As[r * 36 + 24 + kb] = to_tf32(aS[q].w);
            int k = idx >> 5, nb = idx & 31;
            int c = (k & 3) * 8 + (k >> 2);
            Bs[(nb * 4 + 0) * 36 + c] = to_tf32(bS[q].x);
            Bs[(nb * 4 + 1) * 36 + c] = to_tf32(bS[q].y);
            Bs[(nb * 4 + 2) * 36 + c] = to_tf32(bS[q].z);
            Bs[(nb * 4 + 3) * 36 + c] = to_tf32(bS[q].w);
        }
    }
    __syncthreads();

    float acc[2][8][4];
    #pragma unroll
    for (int mt = 0; mt < 2; mt++)
        #pragma unroll
        for (int j = 0; j < 8; j++)
            #pragma unroll
            for (int q = 0; q < 4; q++) acc[mt][j][q] = 0.f;

    const int NKT = KK / 32;   // 128
    for (int kt = 0; kt < NKT; kt++) {
        const int s = kt & 1;

        // prefetch next tile into registers
        if (kt + 1 < NKT) {
            #pragma unroll
            for (int q = 0; q < 4; q++) {
                int idx = tid + q * 256;
                int r = idx >> 3, kb = idx & 7;
                int k = idx >> 5, nb = idx & 31;
                aS[q] = *(const float4*)(Ag + (size_t)r * KK + (kt + 1) * 32 + kb * 4);
                bS[q] = *(const float4*)(Bg + (size_t)((kt + 1) * 32 + k) * N + nb * 4);
            }
        }

        // ---- compute on stage s ----
        const float* As = sm + s * STG_F;
        const float* Bs = As + 128 * 36;
        #pragma unroll
        for (int h = 0; h < 2; h++) {
            float4 af[2][2];
            #pragma unroll
            for (int mt = 0; mt < 2; mt++)
                #pragma unroll
                for (int rr = 0; rr < 2; rr++)
                    af[mt][rr] = *(const float4*)&As[(wm * 32 + mt * 16 + rr * 8 + g) * 36
                                                     + t * 8 + h * 4];
            float4 bf[8];
            #pragma unroll
            for (int j = 0; j < 8; j++)
                bf[j] = *(const float4*)&Bs[(wn * 64 + j * 8 + g) * 36 + t * 8 + h * 4];

            #pragma unroll
            for (int ks = 0; ks < 2; ks++) {
                #pragma unroll
                for (int mt = 0; mt < 2; mt++) {
                    float a0 = (ks == 0) ? af[mt][0].x : af[mt][0].z;
                    float a2 = (ks == 0) ? af[mt][0].y : af[mt][0].w;
                    float a1 = (ks == 0) ? af[mt][1].x : af[mt][1].z;
                    float a3 = (ks == 0) ? af[mt][1].y : af[mt][1].w;
                    #pragma unroll
                    for (int j = 0; j < 8; j++) {
                        float b0 = (ks == 0) ? bf[j].x : bf[j].z;
                        float b1 = (ks == 0) ? bf[j].y : bf[j].w;
                        mma1688(acc[mt][j], a0, a1, a2, a3, b0, b1);
                    }
                }
            }
        }

        // store prefetched tile into stage s^1
        if (kt + 1 < NKT) {
            float* Aw = sm + (s ^ 1) * STG_F;
            float* Bw = Aw + 128 * 36;
            #pragma unroll
            for (int q = 0; q < 4; q++) {
                int idx = tid + q * 256;
                int r = idx >> 3, kb = idx & 7;
                Aw[r * 36 + 0  + kb] = to_tf32(aS[q].x);
                Aw[r * 36 + 8  + kb] = to_tf32(aS[q].y);
                Aw[r * 36 + 16 + kb] = to_tf32(aS[q].z);
                Aw[r * 36 + 24 + kb] = to_tf32(aS[q].w);
                int k = idx >> 5, nb = idx & 31;
                int c = (k & 3) * 8 + (k >> 2);
                Bw[(nb * 4 + 0) * 36 + c] = to_tf32(bS[q].x);
                Bw[(nb * 4 + 1) * 36 + c] = to_tf32(bS[q].y);
                Bw[(nb * 4 + 2) * 36 + c] = to_tf32(bS[q].z);
                Bw[(nb * 4 + 3) * 36 + c] = to_tf32(bS[q].w);
            }
        }
        __syncthreads();
    }

    // ---- epilogue: c0,c1 at (row g, col 2t), c2,c3 at row g+8 ----
    #pragma unroll
    for (int mt = 0; mt < 2; mt++) {
        int row = bm * 128 + wm * 32 + mt * 16 + g;
        #pragma unroll
        for (int j = 0; j < 8; j++) {
            int col = bn * 128 + wn * 64 + j * 8 + 2 * t;
            *(float2*)&C[(size_t)row * N + col] =
                make_float2(acc[mt][j][0], acc[mt][j][1]);
            *(float2*)&C[(size_t)(row + 8) * N + col] =
                make_float2(acc[mt][j][2], acc[mt][j][3]);
        }
    }
}

__global__ __launch_bounds__(256, 1)
void tc_gemm_qkv_kernel(const float* __restrict__ A, const float* __restrict__ B)
{
    tc_gemm(A, B, g_qkv, QKVN);
}

__global__ __launch_bounds__(256, 1)
void tc_gemm_out_kernel(const float* __restrict__ B, float* __restrict__ C)
{
    tc_gemm(g_attn, B, C, HH);
}

// =====================================================================
// Copy fp KV cache into prefix of g_kall / g_vall
// =====================================================================
__global__ void copy_cache_kernel(const float4* __restrict__ kc,
                                  const float4* __restrict__ vc)
{
    const int perb = PP * NKVH * DD / 4;
    int i = blockIdx.x * blockDim.x + threadIdx.x;
    if (i >= BB * perb) return;
    int b = i / perb, r = i - b * perb;
    size_t dst = (size_t)b * (TT * NKVH * DD / 4) + r;
    ((float4*)g_kall)[dst] = kc[i];
    ((float4*)g_vall)[dst] = vc[i];
}

// =====================================================================
// RoPE on q (in place in g_qkv) and k (scattered to g_kall suffix),
// v copied to g_vall suffix. One block per token.
// =====================================================================
__global__ void rope_scatter_kernel(const float* __restrict__ cosp,
                                    const float* __restrict__ sinp)
{
    const int token = blockIdx.x;
    const int b = token / SS, s = token - b * SS;
    float* base = g_qkv + (size_t)token * QKVN;
    const float* cs = cosp + s * DD;
    const float* sn = sinp + s * DD;
    const int tid = threadIdx.x;

    for (int idx = tid; idx < NQH * 64; idx += blockDim.x) {
        int hd = idx >> 6, d = idx & 63;
        float* p = base + hd * DD;
        float x1 = p[d], x2 = p[d + 64];
        p[d]      = x1 * cs[d]      - x2 * sn[d];
        p[d + 64] = x2 * cs[d + 64] + x1 * sn[d + 64];
    }
    for (int idx = tid; idx < NKVH * 64; idx += blockDim.x) {
        int hd = idx >> 6, d = idx & 63;
        const float* p = base + NQH * DD + hd * DD;
        float x1 = p[d], x2 = p[d + 64];
        float* o = g_kall + ((size_t)((b * TT + PP + s) * NKVH + hd)) * DD;
        o[d]      = x1 * cs[d]      - x2 * sn[d];
        o[d + 64] = x2 * cs[d + 64] + x1 * sn[d + 64];
    }
    for (int idx = tid; idx < NKVH * DD; idx += blockDim.x) {
        int hd = idx >> 7, d = idx & 127;
        g_vall[((size_t)((b * TT + PP + s) * NKVH + hd)) * DD + d] =
            base[(NQH + NKVH) * DD + hd * DD + d];
    }
}

// =====================================================================
// Flash attention, fp32, causal with cache offset (unchanged from R9 pass).
// =====================================================================
#define ATT_SMEM (3 * 64 * 32 * 16 + 64 * 64 * 4)   // 114688 B

__global__ __launch_bounds__(256, 1)
void flash_attn_kernel()
{
    extern __shared__ float4 smem4[];
    float4* Qs = smem4;
    float4* Ks = Qs + 64 * 32;
    float4* Vs = Ks + 64 * 32;
    float*  Pb = (float*)(Vs + 64 * 32);

    const int tid = threadIdx.x;
    const int tx = tid & 15, ty = tid >> 4;
    const int m0 = ty * 4, n0 = tx * 4;
    const int qb = blockIdx.x, h = blockIdx.y, b = blockIdx.z;
    const int kvh = h >> 2;
    const int q0 = qb * 64;

    for (int i = tid; i < 64 * 32; i += 256) {
        int m = i >> 5, c4 = i & 31;
        float4 v = *(const float4*)(g_qkv + (size_t)(b * SS + q0 + m) * QKVN + h * DD + c4 * 4);
        Qs[m * 32 + (c4 ^ ((m >> 2) & 7))] = v;
    }

    float acc[4][8];
    #pragma unroll
    for (int i = 0; i < 4; i++)
        #pragma unroll
        for (int j = 0; j < 8; j++) acc[i][j] = 0.f;
    float mrun[4] = {-1e30f, -1e30f, -1e30f, -1e30f};
    float lrun[4] = {0.f, 0.f, 0.f, 0.f};

    const int ntiles = (PP + q0) / 64 + 1;
    for (int kt = 0; kt < ntiles; kt++) {
        const int t0 = kt * 64;
        __syncthreads();
        for (int i = tid; i < 64 * 32; i += 256) {
            int r = i >> 5, c4 = i & 31;
            size_t g = ((size_t)((b * TT + t0 + r) * NKVH + kvh)) * DD + c4 * 4;
            Ks[r * 32 + (c4 ^ ((r >> 2) & 7))] = *(const float4*)(g_kall + g);
            Vs[r * 32 + c4]                    = *(const float4*)(g_vall + g);
        }
        __syncthreads();

        float sc[4][4];
        #pragma unroll
        for (int i = 0; i < 4; i++)
            #pragma unroll
            for (int j = 0; j < 4; j++) sc[i][j] = 0.f;
        #pragma unroll 4
        for (int k4 = 0; k4 < 32; k4++) {
            float4 qv[4], kv[4];
            #pragma unroll
            for (int i = 0; i < 4; i++)
                qv[i] = Qs[(m0 + i) * 32 + (k4 ^ (((m0 + i) >> 2) & 7))];
            #pragma unroll
            for (int j = 0; j < 4; j++)
                kv[j] = Ks[(n0 + j) * 32 + (k4 ^ (((n0 + j) >> 2) & 7))];
            #pragma unroll
            for (int i = 0; i < 4; i++)
                #pragma unroll
                for (int j = 0; j < 4; j++)
                    sc[i][j] += qv[i].x * kv[j].x + qv[i].y * kv[j].y
                              + qv[i].z * kv[j].z + qv[i].w * kv[j].w;
        }

        const bool edge = (t0 + 64 > PP + q0);
        #pragma unroll
        for (int i = 0; i < 4; i++) {
            const int qpos = PP + q0 + m0 + i;
            float mx = -1e30f;
            #pragma unroll
            for (int j = 0; j < 4; j++) {
                float v = sc[i][j] * ATTN_SCALE;
                if (edge && (t0 + n0 + j > qpos)) v = -1e30f;
                sc[i][j] = v;
                mx = fmaxf(mx, v);
            }
            #pragma unroll
            for (int o = 8; o >= 1; o >>= 1)
                mx = fmaxf(mx, __shfl_xor_sync(0xffffffffu, mx, o));
            float mnew = fmaxf(mrun[i], mx);
            float alpha = __expf(mrun[i] - mnew);
            mrun[i] = mnew;
            float rs = 0.f;
            #pragma unroll
            for (int j = 0; j < 4; j++) {
                float p = __expf(sc[i][j] - mnew);
                sc[i][j] = p;
                rs += p;
            }
            #pragma unroll
            for (int o = 8; o >= 1; o >>= 1)
                rs += __shfl_xor_sync(0xffffffffu, rs, o);
            lrun[i] = lrun[i] * alpha + rs;
            #pragma unroll
            for (int j = 0; j < 8; j++) acc[i][j] *= alpha;
        }

        #pragma unroll
        for (int i = 0; i < 4; i++)
            *(float4*)&Pb[(m0 + i) * 64 + n0] =
                make_float4(sc[i][0], sc[i][1], sc[i][2], sc[i][3]);
        __syncthreads();

        #pragma unroll 4
        for (int k = 0; k < 64; k++) {
            float4 v0 = Vs[k * 32 + 2 * tx];
            float4 v1 = Vs[k * 32 + 2 * tx + 1];
            #pragma unroll
            for (int i = 0; i < 4; i++) {
                float p = Pb[(m0 + i) * 64 + k];
                acc[i][0] += p * v0.x; acc[i][1] += p * v0.y;
                acc[i][2] += p * v0.z; acc[i][3] += p * v0.w;
                acc[i][4] += p * v1.x; acc[i][5] += p * v1.y;
                acc[i][6] += p * v1.z; acc[i][7] += p * v1.w;
            }
        }
    }

    #pragma unroll
    for (int i = 0; i < 4; i++) {
        float inv = 1.f / lrun[i];
        float* o = g_attn + (size_t)(b * SS + q0 + m0 + i) * (NQH * DD) + h * DD + tx * 8;
        *(float4*)o       = make_float4(acc[i][0] * inv, acc[i][1] * inv,
                                        acc[i][2] * inv, acc[i][3] * inv);
        *(float4*)(o + 4) = make_float4(acc[i][4] * inv, acc[i][5] * inv,
                                        acc[i][6] * inv, acc[i][7] * inv);
    }
}

// =====================================================================
// Launch — inputs identified by element count:
//   hidden 8388608 | w_qkv 25165824 | w_o 16777216
//   cos/sin 131072 (cos first) | k/v cache 2097152 (k first)
// =====================================================================
extern "C" void kernel_launch(void* const* d_in, const int* in_sizes, int n_in,
                              void* d_out, int out_size)
{
    (void)out_size;
    const float *hidden = 0, *wqkv = 0, *wo = 0, *cosp = 0, *sinp = 0, *kc = 0, *vc = 0;
    for (int i = 0; i < n_in; i++) {
        const float* p = (const float*)d_in[i];
        switch (in_sizes[i]) {
            case 8388608:  hidden = p; break;
            case 25165824: wqkv = p; break;
            case 16777216: wo = p; break;
            case 131072:   if (!cosp) cosp = p; else sinp = p; break;
            case 2097152:  if (!kc) kc = p; else vc = p; break;
            default: break;
        }
    }
    float* out = (float*)d_out;

    cudaFuncSetAttribute(flash_attn_kernel,
                         cudaFuncAttributeMaxDynamicSharedMemorySize, ATT_SMEM);
    cudaFuncSetAttribute(tc_gemm_qkv_kernel,
                         cudaFuncAttributeMaxDynamicSharedMemorySize, GEMM_SMEM);
    cudaFuncSetAttribute(tc_gemm_out_kernel,
                         cudaFuncAttributeMaxDynamicSharedMemorySize, GEMM_SMEM);

    // 1) fused QKV projection (mma.sync tf32) -> g_qkv
    tc_gemm_qkv_kernel<<<dim3(QKVN / 128, MM / 128), 256, GEMM_SMEM>>>(hidden, wqkv);

    // 2) KV cache into prefix of g_kall/g_vall
    {
        int n4 = BB * PP * NKVH * DD / 4;
        copy_cache_kernel<<<(n4 + 255) / 256, 256>>>((const float4*)kc,
                                                     (const float4*)vc);
    }

    // 3) RoPE on q (in place) and k, scatter new k/v into suffix
    rope_scatter_kernel<<<MM, 256>>>(cosp, sinp);

    // 4) causal GQA flash attention -> g_attn
    flash_attn_kernel<<<dim3(SS / 64, NQH, BB), 256, ATT_SMEM>>>();

    // 5) output projection (mma.sync tf32) -> d_out
    tc_gemm_out_kernel<<<dim3(HH / 128, MM / 128), 256, GEMM_SMEM>>>(wo, out);
}

// round 16
// speedup vs baseline: 1.4232x; 1.4232x over previous
#include <cuda_runtime.h>
#include <math.h>
#include <stdint.h>

// ---------------- problem constants ----------------
#define BB   2
#define SS   1024
#define PP   1024
#define TT   2048           // P + S
#define HH   4096
#define NQH  32
#define NKVH 8
#define DD   128
#define GQ   4              // NQH / NKVH
#define MM   (BB*SS)        // 2048 token rows
#define QKVN ((NQH + 2*NKVH)*DD)   // 6144
#define KK   4096           // GEMM K dim for both projections
#define ATTN_SCALE 0.08838834764831845f   // 1/sqrt(128)

// ---------------- device scratch (no allocation allowed) ----------------
__device__ float g_qkv [(size_t)MM * QKVN];           // 50.3 MB
__device__ float g_kall[(size_t)BB * TT * NKVH * DD]; // 16.8 MB
__device__ float g_vall[(size_t)BB * TT * NKVH * DD]; // 16.8 MB
__device__ float g_attn[(size_t)MM * NQH * DD];       // 33.5 MB

// =====================================================================
// tf32 helpers (mma.sync — baseline sm_80 feature, OK on plain sm_103)
// =====================================================================
__device__ __forceinline__ float to_tf32(float x) {
    uint32_t h;
    asm("cvt.rna.tf32.f32 %0, %1;" : "=r"(h) : "f"(x));
    return __uint_as_float(h);
}

__device__ __forceinline__ void mma1688(float* c,
                                        float a0, float a1, float a2, float a3,
                                        float b0, float b1) {
    asm volatile(
        "mma.sync.aligned.m16n8k8.row.col.f32.tf32.tf32.f32 "
        "{%0,%1,%2,%3}, {%4,%5,%6,%7}, {%8,%9}, {%0,%1,%2,%3};"
        : "+f"(c[0]), "+f"(c[1]), "+f"(c[2]), "+f"(c[3])
        : "r"(__float_as_uint(a0)), "r"(__float_as_uint(a1)),
          "r"(__float_as_uint(a2)), "r"(__float_as_uint(a3)),
          "r"(__float_as_uint(b0)), "r"(__float_as_uint(b1)));
}

// =====================================================================
// tf32 tensor-core GEMM: C[M,N] = A[M,K=4096] @ B[K,N]  (both row-major)
// CTA 128x128, BK=32, 8 warps (4x2) of 32x64, double-buffered SMEM.
//
// SMEM permuted layout: element k of a row goes to column (k%4)*8 + k/4,
// row stride 36 floats -> fragments load as conflict-free LDS.128.
//
// B fill (fixed this round): thread handles one output column n and the
// 4 k-values {bk, bk+4, bk+8, bk+12}, bk = (j'&1)*16 + (j'>>1). Those k's
// map to contiguous permuted columns 4j'..4j'+3 -> a single aligned
// STS.128 at n*36 + 4j'; per-phase banks 4n%32 are all distinct ->
// conflict-free (was 16-way conflicted). LDGs remain coalesced.
// =====================================================================
#define GEMM_SMEM (2 * (128*36 + 128*36) * 4)   // 73728
#define STG_F     (128*36 + 128*36)             // floats per stage

__device__ __forceinline__ void tc_gemm(const float* __restrict__ A,
                                        const float* __restrict__ B,
                                        float* __restrict__ C, int N)
{
    extern __shared__ float sm[];
    const int tid  = threadIdx.x;
    const int wid  = tid >> 5, lane = tid & 31;
    const int wm   = wid & 3,  wn   = wid >> 2;   // warp at (wm*32, wn*64)
    const int g    = lane >> 2, t   = lane & 3;
    const int bm   = blockIdx.y, bn = blockIdx.x;

    const float* Ag = A + (size_t)(bm * 128) * KK;
    const float* Bg = B + bn * 128;

    float4 aS[4], bS[4];

    // ---- prologue: load kt=0 ----
    #pragma unroll
    for (int q = 0; q < 4; q++) {
        int idx = tid + q * 256;
        int r = idx >> 3, kb = idx & 7;                 // A: row r, float4 kb
        aS[q] = *(const float4*)(Ag + (size_t)r * KK + kb * 4);
        int n = idx & 127, jp = idx >> 7;               // B: col n, perm block jp
        int bk = ((jp & 1) << 4) + (jp >> 1);
        bS[q].x = Bg[(size_t)(bk + 0)  * N + n];
        bS[q].y = Bg[(size_t)(bk + 4)  * N + n];
        bS[q].z = Bg[(size_t)(bk + 8)  * N + n];
        bS[q].w = Bg[(size_t)(bk + 12) * N + n];
    }
    {
        float* As = sm;
        float* Bs = sm + 128 * 36;
        #pragma unroll
        for (int q = 0; q < 4; q++) {
            int idx = tid + q * 256;
            int r = idx >> 3, kb = idx & 7;
            As[r * 36 + 0  + kb] = to_tf32(aS[q].x);
            As[r * 36 + 8  + kb] = to_tf32(aS[q].y);
            As[r * 36 + 16 + kb] = to_tf32(aS[q].z);
            As[r * 36 + 24 + kb] = to_tf32(aS[q].w);
            int n = idx & 127, jp = idx >> 7;
            *(float4*)&Bs[n * 36 + jp * 4] = make_float4(
                to_tf32(bS[q].x), to_tf32(bS[q].y),
                to_tf32(bS[q].z), to_tf32(bS[q].w));
        }
    }
    __syncthreads();

    float acc[2][8][4];
    #pragma unroll
    for (int mt = 0; mt < 2; mt++)
        #pragma unroll
        for (int j = 0; j < 8; j++)
            #pragma unroll
            for (int q = 0; q < 4; q++) acc[mt][j][q] = 0.f;

    const int NKT = KK / 32;   // 128
    for (int kt = 0; kt < NKT; kt++) {
        const int s = kt & 1;

        // prefetch next tile into registers
        if (kt + 1 < NKT) {
            #pragma unroll
            for (int q = 0; q < 4; q++) {
                int idx = tid + q * 256;
                int r = idx >> 3, kb = idx & 7;
                aS[q] = *(const float4*)(Ag + (size_t)r * KK + (kt + 1) * 32 + kb * 4);
                int n = idx & 127, jp = idx >> 7;
                int bk = (kt + 1) * 32 + ((jp & 1) << 4) + (jp >> 1);
                bS[q].x = Bg[(size_t)(bk + 0)  * N + n];
                bS[q].y = Bg[(size_t)(bk + 4)  * N + n];
                bS[q].z = Bg[(size_t)(bk + 8)  * N + n];
                bS[q].w = Bg[(size_t)(bk + 12) * N + n];
            }
        }

        // ---- compute on stage s ----
        const float* As = sm + s * STG_F;
        const float* Bs = As + 128 * 36;
        #pragma unroll
        for (int h = 0; h < 2; h++) {
            float4 af[2][2];
            #pragma unroll
            for (int mt = 0; mt < 2; mt++)
                #pragma unroll
                for (int rr = 0; rr < 2; rr++)
                    af[mt][rr] = *(const float4*)&As[(wm * 32 + mt * 16 + rr * 8 + g) * 36
                                                     + t * 8 + h * 4];
            float4 bf[8];
            #pragma unroll
            for (int j = 0; j < 8; j++)
                bf[j] = *(const float4*)&Bs[(wn * 64 + j * 8 + g) * 36 + t * 8 + h * 4];

            #pragma unroll
            for (int ks = 0; ks < 2; ks++) {
                #pragma unroll
                for (int mt = 0; mt < 2; mt++) {
                    float a0 = (ks == 0) ? af[mt][0].x : af[mt][0].z;
                    float a2 = (ks == 0) ? af[mt][0].y : af[mt][0].w;
                    float a1 = (ks == 0) ? af[mt][1].x : af[mt][1].z;
                    float a3 = (ks == 0) ? af[mt][1].y : af[mt][1].w;
                    #pragma unroll
                    for (int j = 0; j < 8; j++) {
                        float b0 = (ks == 0) ? bf[j].x : bf[j].z;
                        float b1 = (ks == 0) ? bf[j].y : bf[j].w;
                        mma1688(acc[mt][j], a0, a1, a2, a3, b0, b1);
                    }
                }
            }
        }

        // store prefetched tile into stage s^1
        if (kt + 1 < NKT) {
            float* Aw = sm + (s ^ 1) * STG_F;
            float* Bw = Aw + 128 * 36;
            #pragma unroll
            for (int q = 0; q < 4; q++) {
                int idx = tid + q * 256;
                int r = idx >> 3, kb = idx & 7;
                Aw[r * 36 + 0  + kb] = to_tf32(aS[q].x);
                Aw[r * 36 + 8  + kb] = to_tf32(aS[q].y);
                Aw[r * 36 + 16 + kb] = to_tf32(aS[q].z);
                Aw[r * 36 + 24 + kb] = to_tf32(aS[q].w);
                int n = idx & 127, jp = idx >> 7;
                *(float4*)&Bw[n * 36 + jp * 4] = make_float4(
                    to_tf32(bS[q].x), to_tf32(bS[q].y),
                    to_tf32(bS[q].z), to_tf32(bS[q].w));
            }
        }
        __syncthreads();
    }

    // ---- epilogue: c0,c1 at (row g, col 2t), c2,c3 at row g+8 ----
    #pragma unroll
    for (int mt = 0; mt < 2; mt++) {
        int row = bm * 128 + wm * 32 + mt * 16 + g;
        #pragma unroll
        for (int j = 0; j < 8; j++) {
            int col = bn * 128 + wn * 64 + j * 8 + 2 * t;
            *(float2*)&C[(size_t)row * N + col] =
                make_float2(acc[mt][j][0], acc[mt][j][1]);
            *(float2*)&C[(size_t)(row + 8) * N + col] =
                make_float2(acc[mt][j][2], acc[mt][j][3]);
        }
    }
}

__global__ __launch_bounds__(256, 1)
void tc_gemm_qkv_kernel(const float* __restrict__ A, const float* __restrict__ B)
{
    tc_gemm(A, B, g_qkv, QKVN);
}

__global__ __launch_bounds__(256, 1)
void tc_gemm_out_kernel(const float* __restrict__ B, float* __restrict__ C)
{
    tc_gemm(g_attn, B, C, HH);
}

// =====================================================================
// Copy fp KV cache into prefix of g_kall / g_vall
// =====================================================================
__global__ void copy_cache_kernel(const float4* __restrict__ kc,
                                  const float4* __restrict__ vc)
{
    const int perb = PP * NKVH * DD / 4;
    int i = blockIdx.x * blockDim.x + threadIdx.x;
    if (i >= BB * perb) return;
    int b = i / perb, r = i - b * perb;
    size_t dst = (size_t)b * (TT * NKVH * DD / 4) + r;
    ((float4*)g_kall)[dst] = kc[i];
    ((float4*)g_vall)[dst] = vc[i];
}

// =====================================================================
// RoPE on q (in place in g_qkv) and k (scattered to g_kall suffix),
// v copied to g_vall suffix. One block per token.
// =====================================================================
__global__ void rope_scatter_kernel(const float* __restrict__ cosp,
                                    const float* __restrict__ sinp)
{
    const int token = blockIdx.x;
    const int b = token / SS, s = token - b * SS;
    float* base = g_qkv + (size_t)token * QKVN;
    const float* cs = cosp + s * DD;
    const float* sn = sinp + s * DD;
    const int tid = threadIdx.x;

    for (int idx = tid; idx < NQH * 64; idx += blockDim.x) {
        int hd = idx >> 6, d = idx & 63;
        float* p = base + hd * DD;
        float x1 = p[d], x2 = p[d + 64];
        p[d]      = x1 * cs[d]      - x2 * sn[d];
        p[d + 64] = x2 * cs[d + 64] + x1 * sn[d + 64];
    }
    for (int idx = tid; idx < NKVH * 64; idx += blockDim.x) {
        int hd = idx >> 6, d = idx & 63;
        const float* p = base + NQH * DD + hd * DD;
        float x1 = p[d], x2 = p[d + 64];
        float* o = g_kall + ((size_t)((b * TT + PP + s) * NKVH + hd)) * DD;
        o[d]      = x1 * cs[d]      - x2 * sn[d];
        o[d + 64] = x2 * cs[d + 64] + x1 * sn[d + 64];
    }
    for (int idx = tid; idx < NKVH * DD; idx += blockDim.x) {
        int hd = idx >> 7, d = idx & 127;
        g_vall[((size_t)((b * TT + PP + s) * NKVH + hd)) * DD + d] =
            base[(NQH + NKVH) * DD + hd * DD + d];
    }
}

// =====================================================================
// Flash attention, fp32, causal with cache offset.
// This round: KV tile 32 rows (smem 73728 B) + launch_bounds(256,2)
// -> 2 CTAs/SM. V columns per thread remapped to {tx, 16+tx} and K
// swizzle to (r>>1)&7 so all inner-loop LDS are conflict-free.
// =====================================================================
#define ATT_SMEM (64*32*16 + 2*32*32*16 + 64*32*4)   // 73728 B

__global__ __launch_bounds__(256, 2)
void flash_attn_kernel()
{
    extern __shared__ float4 smem4[];
    float4* Qs = smem4;                  // [64][32] swizzled by (m>>2)&7
    float4* Ks = Qs + 64 * 32;           // [32][32] swizzled by (r>>1)&7
    float4* Vs = Ks + 32 * 32;           // [32][32] row-major
    float*  Pb = (float*)(Vs + 32 * 32); // [64][32]

    const int tid = threadIdx.x;
    const int tx = tid & 15, ty = tid >> 4;
    const int m0 = ty * 4, n0 = tx * 2;
    const int qb = blockIdx.x, h = blockIdx.y, b = blockIdx.z;
    const int kvh = h >> 2;
    const int q0 = qb * 64;

    // load Q tile (already roped)
    for (int i = tid; i < 64 * 32; i += 256) {
        int m = i >> 5, c4 = i & 31;
        float4 v = *(const float4*)(g_qkv + (size_t)(b * SS + q0 + m) * QKVN + h * DD + c4 * 4);
        Qs[m * 32 + (c4 ^ ((m >> 2) & 7))] = v;
    }

    float acc[4][8];
    #pragma unroll
    for (int i = 0; i < 4; i++)
        #pragma unroll
        for (int j = 0; j < 8; j++) acc[i][j] = 0.f;
    float mrun[4] = {-1e30f, -1e30f, -1e30f, -1e30f};
    float lrun[4] = {0.f, 0.f, 0.f, 0.f};

    const int ntiles = (PP + q0) / 32 + 2;   // last two tiles straddle the diagonal
    for (int kt = 0; kt < ntiles; kt++) {
        const int t0 = kt * 32;
        __syncthreads();   // previous PV done before overwriting K/V
        for (int i = tid; i < 32 * 32; i += 256) {
            int r = i >> 5, c4 = i & 31;
            size_t g = ((size_t)((b * TT + t0 + r) * NKVH + kvh)) * DD + c4 * 4;
            Ks[r * 32 + (c4 ^ ((r >> 1) & 7))] = *(const float4*)(g_kall + g);
            Vs[r * 32 + c4]                    = *(const float4*)(g_vall + g);
        }
        __syncthreads();

        // ---- scores: sc[4][2] = Q(m0..m0+3) . K(n0..n0+1) over D=128 ----
        float sc[4][2];
        #pragma unroll
        for (int i = 0; i < 4; i++) { sc[i][0] = 0.f; sc[i][1] = 0.f; }
        #pragma unroll 4
        for (int k4 = 0; k4 < 32; k4++) {
            float4 qv[4], kv[2];
            #pragma unroll
            for (int i = 0; i < 4; i++)
                qv[i] = Qs[(m0 + i) * 32 + (k4 ^ (((m0 + i) >> 2) & 7))];
            #pragma unroll
            for (int j = 0; j < 2; j++)
                kv[j] = Ks[(n0 + j) * 32 + (k4 ^ (((n0 + j) >> 1) & 7))];
            #pragma unroll
            for (int i = 0; i < 4; i++)
                #pragma unroll
                for (int j = 0; j < 2; j++)
                    sc[i][j] += qv[i].x * kv[j].x + qv[i].y * kv[j].y
                              + qv[i].z * kv[j].z + qv[i].w * kv[j].w;
        }

        // ---- online softmax update (rows split across 16 tx lanes) ----
        const bool edge = (t0 + 32 > PP + q0);
        #pragma unroll
        for (int i = 0; i < 4; i++) {
            const int qpos = PP + q0 + m0 + i;
            float mx = -1e30f;
            #pragma unroll
            for (int j = 0; j < 2; j++) {
                float v = sc[i][j] * ATTN_SCALE;
                if (edge && (t0 + n0 + j > qpos)) v = -1e30f;
                sc[i][j] = v;
                mx = fmaxf(mx, v);
            }
            #pragma unroll
            for (int o = 8; o >= 1; o >>= 1)
                mx = fmaxf(mx, __shfl_xor_sync(0xffffffffu, mx, o));
            float mnew = fmaxf(mrun[i], mx);
            float alpha = __expf(mrun[i] - mnew);
            mrun[i] = mnew;
            float rs = 0.f;
            #pragma unroll
            for (int j = 0; j < 2; j++) {
                float p = __expf(sc[i][j] - mnew);
                sc[i][j] = p;
                rs += p;
            }
            #pragma unroll
            for (int o = 8; o >= 1; o >>= 1)
                rs += __shfl_xor_sync(0xffffffffu, rs, o);
            lrun[i] = lrun[i] * alpha + rs;
            #pragma unroll
            for (int j = 0; j < 8; j++) acc[i][j] *= alpha;
        }

        // write P row-major (float2 stores)
        #pragma unroll
        for (int i = 0; i < 4; i++)
            *(float2*)&Pb[(m0 + i) * 32 + n0] = make_float2(sc[i][0], sc[i][1]);
        __syncthreads();

        // ---- PV: thread covers output cols {4tx..4tx+3, 64+4tx..64+4tx+3} ----
        #pragma unroll 4
        for (int k = 0; k < 32; k++) {
            float4 v0 = Vs[k * 32 + tx];        // cols 4tx..4tx+3
            float4 v1 = Vs[k * 32 + 16 + tx];   // cols 64+4tx..64+4tx+3
            #pragma unroll
            for (int i = 0; i < 4; i++) {
                float p = Pb[(m0 + i) * 32 + k];
                acc[i][0] += p * v0.x; acc[i][1] += p * v0.y;
                acc[i][2] += p * v0.z; acc[i][3] += p * v0.w;
                acc[i][4] += p * v1.x; acc[i][5] += p * v1.y;
                acc[i][6] += p * v1.z; acc[i][7] += p * v1.w;
            }
        }
    }

    // epilogue: normalize and write [B,S,NQ*D] into g_attn (device symbol)
    #pragma unroll
    for (int i = 0; i < 4; i++) {
        float inv = 1.f / lrun[i];
        float* o = g_attn + (size_t)(b * SS + q0 + m0 + i) * (NQH * DD) + h * DD + tx * 4;
        *(float4*)o        = make_float4(acc[i][0] * inv, acc[i][1] * inv,
                                         acc[i][2] * inv, acc[i][3] * inv);
        *(float4*)(o + 64) = make_float4(acc[i][4] * inv, acc[i][5] * inv,
                                         acc[i][6] * inv, acc[i][7] * inv);
    }
}

// =====================================================================
// Launch — inputs identified by element count:
//   hidden 8388608 | w_qkv 25165824 | w_o 16777216
//   cos/sin 131072 (cos first) | k/v cache 2097152 (k first)
// =====================================================================
extern "C" void kernel_launch(void* const* d_in, const int* in_sizes, int n_in,
                              void* d_out, int out_size)
{
    (void)out_size;
    const float *hidden = 0, *wqkv = 0, *wo = 0, *cosp = 0, *sinp = 0, *kc = 0, *vc = 0;
    for (int i = 0; i < n_in; i++) {
        const float* p = (const float*)d_in[i];
        switch (in_sizes[i]) {
            case 8388608:  hidden = p; break;
            case 25165824: wqkv = p; break;
            case 16777216: wo = p; break;
            case 131072:   if (!cosp) cosp = p; else sinp = p; break;
            case 2097152:  if (!kc) kc = p; else vc = p; break;
            default: break;
        }
    }
    float* out = (float*)d_out;

    cudaFuncSetAttribute(flash_attn_kernel,
                         cudaFuncAttributeMaxDynamicSharedMemorySize, ATT_SMEM);
    cudaFuncSetAttribute(tc_gemm_qkv_kernel,
                         cudaFuncAttributeMaxDynamicSharedMemorySize, GEMM_SMEM);
    cudaFuncSetAttribute(tc_gemm_out_kernel,
                         cudaFuncAttributeMaxDynamicSharedMemorySize, GEMM_SMEM);

    // 1) fused QKV projection (mma.sync tf32) -> g_qkv
    tc_gemm_qkv_kernel<<<dim3(QKVN / 128, MM / 128), 256, GEMM_SMEM>>>(hidden, wqkv);

    // 2) KV cache into prefix of g_kall/g_vall
    {
        int n4 = BB * PP * NKVH * DD / 4;
        copy_cache_kernel<<<(n4 + 255) / 256, 256>>>((const float4*)kc,
                                                     (const float4*)vc);
    }

    // 3) RoPE on q (in place) and k, scatter new k/v into suffix
    rope_scatter_kernel<<<MM, 256>>>(cosp, sinp);

    // 4) causal GQA flash attention -> g_attn
    flash_attn_kernel<<<dim3(SS / 64, NQH, BB), 256, ATT_SMEM>>>();

    // 5) output projection (mma.sync tf32) -> d_out
    tc_gemm_out_kernel<<<dim3(HH / 128, MM / 128), 256, GEMM_SMEM>>>(wo, out);
}